// round 1
// baseline (speedup 1.0000x reference)
#include <cuda_runtime.h>
#include <math.h>

#define NB 16
#define NH 16
#define NHD 64
#define ND 1024
#define NL 513
#define NP 1024

// Scratch (allocation-free rule: __device__ globals)
__device__ float g_QC[NB*NH*NL*NHD];   // q + content_bias, [b,h,l,hd]
__device__ float g_QP[NB*NH*NL*NHD];   // q + position_bias
__device__ float g_Kt[NB*NH*NL*NHD];   // k, [b,h,l,hd]
__device__ float g_Vt[NB*NH*NL*NHD];   // v, [b,h,l,hd]
__device__ float g_PT[NB*NH*NP*NHD];   // pos projected, transposed: [b,h,p,hd]
__device__ float g_CTX[NB*NL*ND];      // attention output, [b,l,h*64+hd]

// ---------------------------------------------------------------------------
// Generic fp32 SGEMM: C[m,n] = sum_k A[m,k]*Bw[n,k] (+bias), K=1024 fixed.
// BM=BN=128, BK=16, 256 threads, 8x8 micro-tile. EPI selects the epilogue.
// ---------------------------------------------------------------------------
template<int EPI>
__global__ void __launch_bounds__(256)
sgemm_k(const float* __restrict__ A, const float* __restrict__ Bw,
        int M, int N,
        const float* __restrict__ bias,
        const float* __restrict__ cbias, const float* __restrict__ pbias,
        float* __restrict__ out)
{
    __shared__ float As[16][128];
    __shared__ float Bs[16][128];
    const int K = 1024;
    int t  = threadIdx.x;
    int tx = t & 15, ty = t >> 4;
    int m0 = blockIdx.y * 128, n0 = blockIdx.x * 128;
    int lr = t >> 2;          // 0..63
    int lc = (t & 3) << 2;    // 0,4,8,12

    float acc[8][8];
#pragma unroll
    for (int r = 0; r < 8; r++)
#pragma unroll
        for (int c = 0; c < 8; c++) acc[r][c] = 0.f;

    for (int kt = 0; kt < K; kt += 16) {
#pragma unroll
        for (int u = 0; u < 2; u++) {
            int row = lr + (u << 6);
            int m = m0 + row;
            float4 va = make_float4(0.f, 0.f, 0.f, 0.f);
            if (m < M) va = *(const float4*)(A + (size_t)m * K + kt + lc);
            As[lc + 0][row] = va.x; As[lc + 1][row] = va.y;
            As[lc + 2][row] = va.z; As[lc + 3][row] = va.w;
            int n = n0 + row;
            float4 vb = make_float4(0.f, 0.f, 0.f, 0.f);
            if (n < N) vb = *(const float4*)(Bw + (size_t)n * K + kt + lc);
            Bs[lc + 0][row] = vb.x; Bs[lc + 1][row] = vb.y;
            Bs[lc + 2][row] = vb.z; Bs[lc + 3][row] = vb.w;
        }
        __syncthreads();
#pragma unroll
        for (int k = 0; k < 16; k++) {
            float a[8], bb[8];
            *(float4*)&a[0]  = *(const float4*)&As[k][ty * 8];
            *(float4*)&a[4]  = *(const float4*)&As[k][ty * 8 + 4];
            *(float4*)&bb[0] = *(const float4*)&Bs[k][tx * 8];
            *(float4*)&bb[4] = *(const float4*)&Bs[k][tx * 8 + 4];
#pragma unroll
            for (int r = 0; r < 8; r++)
#pragma unroll
                for (int c = 0; c < 8; c++)
                    acc[r][c] += a[r] * bb[c];
        }
        __syncthreads();
    }

#pragma unroll
    for (int r = 0; r < 8; r++) {
        int m = m0 + ty * 8 + r;
        if (m >= M) continue;
        if (EPI == 0) {
            // QKV: m=(b,l), n in [0,3072): part,h,hd. Scatter to QC/QP/K/V.
            int b_ = m / NL, l = m - b_ * NL;
#pragma unroll
            for (int c = 0; c < 8; c++) {
                int n = n0 + tx * 8 + c;
                float v = acc[r][c] + bias[n];
                int part = n >> 10, c1 = n & 1023;
                int hh = c1 >> 6, hd = c1 & 63;
                size_t o = ((((size_t)b_ * NH + hh) * NL + l) << 6) + hd;
                if (part == 0) {
                    g_QC[o] = v + cbias[c1];
                    g_QP[o] = v + pbias[c1];
                } else if (part == 1) {
                    g_Kt[o] = v;
                } else {
                    g_Vt[o] = v;
                }
            }
        } else if (EPI == 1) {
            // POS: m = p, n = (b*H+h)*64+hd, bias indexed by p.
            float bm = bias[m];
#pragma unroll
            for (int c = 0; c < 8; c++) {
                int n = n0 + tx * 8 + c;
                float v = acc[r][c] + bm;
                int bh = n >> 6, hd = n & 63;
                g_PT[((((size_t)bh) << 10) + m) * 64 + hd] = v;
            }
        } else {
            // OUT: plain store
#pragma unroll
            for (int c = 0; c < 8; c++) {
                int n = n0 + tx * 8 + c;
                out[(size_t)m * ND + n] = acc[r][c] + bias[n];
            }
        }
    }
}

// ---------------------------------------------------------------------------
// Fused attention per (b,h,i-tile of 32 queries):
//  score[i,j] = qc_i . k_j + qp_i . posT[j-i+512]   (rel-shift as index map)
//  full-row softmax (scale + mask), then ctx = softmax(scores) @ V
// ---------------------------------------------------------------------------
__global__ void __launch_bounds__(256)
attn_k(const unsigned char* __restrict__ mask, float* __restrict__ ctx)
{
    extern __shared__ float sm[];
    float* sQC  = sm;                  // [64][33]  q+cb transposed
    float* sQP  = sQC + 64 * 33;       // [64][33]  q+pb transposed
    float* sKV  = sQP + 64 * 33;       // [64][68]  K transposed / V direct
    float* sPb  = sKV + 64 * 68;       // [64][97]  pos band transposed
    float* sS   = sPb + 64 * 97;       // [32][520] full score rows
    float* sSum = sS  + 32 * 520;      // [32]

    int t  = threadIdx.x;
    int it = blockIdx.x, h = blockIdx.y, b = blockIdx.z;
    int i0 = it * 32;
    size_t bh = (size_t)b * NH + h;
    const float* QCg = g_QC + bh * NL * NHD;
    const float* QPg = g_QP + bh * NL * NHD;
    const float* Kg  = g_Kt + bh * NL * NHD;
    const float* Vg  = g_Vt + bh * NL * NHD;
    const float* Pg  = g_PT + bh * NP * NHD;

    // load query tiles (transposed, padded)
    for (int idx = t; idx < 2048; idx += 256) {
        int li = idx >> 6, hd = idx & 63;
        int i = i0 + li;
        float vq = 0.f, vp = 0.f;
        if (i < NL) { vq = QCg[i * 64 + hd]; vp = QPg[i * 64 + hd]; }
        sQC[hd * 33 + li] = vq;
        sQP[hd * 33 + li] = vp;
    }

    int tx = t & 15, ty = t >> 4;
    int li0 = ty << 1, lj0 = tx << 2;
    int bA = lj0 - li0 + 31;   // band index for (ii=0, jj=0); >= 1 always

    // ----- score phase -----
    for (int jt = 0; jt < 9; jt++) {
        int j0 = jt << 6;
        __syncthreads();   // protects q-load (jt=0) and sKV/sPb reuse (jt>0)
        for (int idx = t; idx < 4096; idx += 256) {
            int lj = idx >> 6, hd = idx & 63;
            int j = j0 + lj;
            sKV[hd * 68 + lj] = (j < NL) ? Kg[j * 64 + hd] : 0.f;
        }
        int base = j0 - i0 + 481;   // global pos index of band row 0
        for (int idx = t; idx < 6144; idx += 256) {
            int bi = idx >> 6, hd = idx & 63;
            int gi = base + bi;
            sPb[hd * 97 + bi] = ((unsigned)gi < (unsigned)NP) ? Pg[(size_t)gi * 64 + hd] : 0.f;
        }
        __syncthreads();

        float a00=0,a01=0,a02=0,a03=0,a10=0,a11=0,a12=0,a13=0;
#pragma unroll 8
        for (int k = 0; k < 64; k++) {
            float qc0 = sQC[k * 33 + li0];
            float qc1 = sQC[k * 33 + li0 + 1];
            float qp0 = sQP[k * 33 + li0];
            float qp1 = sQP[k * 33 + li0 + 1];
            float4 kv = *(const float4*)&sKV[k * 68 + lj0];
            const float* pr = &sPb[k * 97 + bA - 1];
            float f0 = pr[0], f1 = pr[1], f2 = pr[2], f3 = pr[3], f4 = pr[4];
            a00 += qc0 * kv.x; a01 += qc0 * kv.y; a02 += qc0 * kv.z; a03 += qc0 * kv.w;
            a10 += qc1 * kv.x; a11 += qc1 * kv.y; a12 += qc1 * kv.z; a13 += qc1 * kv.w;
            a00 += qp0 * f1;   a01 += qp0 * f2;   a02 += qp0 * f3;   a03 += qp0 * f4;
            a10 += qp1 * f0;   a11 += qp1 * f1;   a12 += qp1 * f2;   a13 += qp1 * f3;
        }
        int jb = j0 + lj0;
        float* s0 = &sS[li0 * 520];
        float* s1 = &sS[(li0 + 1) * 520];
        if (jb + 0 < NL) { s0[jb + 0] = a00; s1[jb + 0] = a10; }
        if (jb + 1 < NL) { s0[jb + 1] = a01; s1[jb + 1] = a11; }
        if (jb + 2 < NL) { s0[jb + 2] = a02; s1[jb + 2] = a12; }
        if (jb + 3 < NL) { s0[jb + 3] = a03; s1[jb + 3] = a13; }
    }
    __syncthreads();

    // ----- softmax (warp per row-group) -----
    int w = t >> 5, lane = t & 31;
    for (int li = w; li < 32; li += 8) {
        int i = i0 + li;
        if (i >= NL) { if (lane == 0) sSum[li] = 1.f; continue; }
        const unsigned char* mrow = mask + ((size_t)b * NL + i) * NL;
        float* srow = &sS[li * 520];
        float mx = -3.4028235e38f;
        for (int j = lane; j < NL; j += 32) {
            float v = srow[j] * 0.125f;          // scale = 1/sqrt(64)
            if (mrow[j]) v = -3.4028235e38f;     // finfo(f32).min
            srow[j] = v;
            mx = fmaxf(mx, v);
        }
#pragma unroll
        for (int o = 16; o > 0; o >>= 1) mx = fmaxf(mx, __shfl_xor_sync(0xffffffffu, mx, o));
        float s = 0.f;
        for (int j = lane; j < NL; j += 32) {
            float e = expf(srow[j] - mx);
            srow[j] = e;
            s += e;
        }
#pragma unroll
        for (int o = 16; o > 0; o >>= 1) s += __shfl_xor_sync(0xffffffffu, s, o);
        if (lane == 0) sSum[li] = s;
    }

    // ----- AV phase -----
    float o00=0,o01=0,o02=0,o03=0,o10=0,o11=0,o12=0,o13=0;
    for (int jt = 0; jt < 9; jt++) {
        int j0 = jt << 6;
        int jmax = NL - j0; if (jmax > 64) jmax = 64;
        __syncthreads();   // first iter also fences softmax completion
        for (int idx = t; idx < 4096; idx += 256) {
            int lj = idx >> 6, hd = idx & 63;
            int j = j0 + lj;
            sKV[idx] = (j < NL) ? Vg[j * 64 + hd] : 0.f;   // [lj][hd] direct
        }
        __syncthreads();
        const float* s0 = &sS[li0 * 520 + j0];
        const float* s1 = &sS[(li0 + 1) * 520 + j0];
        for (int j = 0; j < jmax; j++) {
            float w0 = s0[j], w1 = s1[j];
            float4 vv = *(const float4*)&sKV[j * 64 + lj0];
            o00 += w0 * vv.x; o01 += w0 * vv.y; o02 += w0 * vv.z; o03 += w0 * vv.w;
            o10 += w1 * vv.x; o11 += w1 * vv.y; o12 += w1 * vv.z; o13 += w1 * vv.w;
        }
    }
    int ia = i0 + li0, ib = ia + 1;
    if (ia < NL) {
        float inv = 1.f / sSum[li0];
        float4 r = make_float4(o00 * inv, o01 * inv, o02 * inv, o03 * inv);
        *(float4*)&ctx[((size_t)b * NL + ia) * ND + h * 64 + lj0] = r;
    }
    if (ib < NL) {
        float inv = 1.f / sSum[li0 + 1];
        float4 r = make_float4(o10 * inv, o11 * inv, o12 * inv, o13 * inv);
        *(float4*)&ctx[((size_t)b * NL + ib) * ND + h * 64 + lj0] = r;
    }
}

// ---------------------------------------------------------------------------
extern "C" void kernel_launch(void* const* d_in, const int* in_sizes, int n_in,
                              void* d_out, int out_size)
{
    const float* x     = (const float*)d_in[0];
    const float* pe    = (const float*)d_in[1];
    const unsigned char* mask = (const unsigned char*)d_in[2];
    const float* qkv_w = (const float*)d_in[3];
    const float* qkv_b = (const float*)d_in[4];
    const float* pos_w = (const float*)d_in[5];
    const float* pos_b = (const float*)d_in[6];
    const float* out_w = (const float*)d_in[7];
    const float* out_b = (const float*)d_in[8];
    const float* cbias = (const float*)d_in[9];
    const float* pbias = (const float*)d_in[10];
    float* out = (float*)d_out;

    float* ctxp = nullptr;
    cudaGetSymbolAddress((void**)&ctxp, g_CTX);

    const int M1 = NB * NL;                 // 8208
    const int ATTN_SMEM = (64*33*2 + 64*68 + 64*97 + 32*520 + 32) * 4;  // 125824 B
    cudaFuncSetAttribute(attn_k, cudaFuncAttributeMaxDynamicSharedMemorySize, ATTN_SMEM);

    dim3 blk(256);
    // QKV projection + scatter (q+biases, k, v)
    sgemm_k<0><<<dim3(3072 / 128, (M1 + 127) / 128), blk>>>(
        x, qkv_w, M1, 3072, qkv_b, cbias, pbias, nullptr);
    // pos projection (independent of QKV)
    sgemm_k<1><<<dim3(16384 / 128, 1024 / 128), blk>>>(
        pos_w, pe, 1024, 16384, pos_b, nullptr, nullptr, nullptr);
    // fused content+position scores, softmax, AV
    attn_k<<<dim3(17, NH, NB), blk, ATTN_SMEM>>>(mask, ctxp);
    // output projection
    sgemm_k<2><<<dim3(1024 / 128, (M1 + 127) / 128), blk>>>(
        ctxp, out_w, M1, 1024, out_b, nullptr, nullptr, out);
}

// round 2
// speedup vs baseline: 1.1201x; 1.1201x over previous
#include <cuda_runtime.h>
#include <cuda_fp16.h>
#include <math.h>

#define NB 16
#define NH 16
#define NHD 64
#define ND 1024
#define NL 513
#define NP 1024

typedef unsigned long long u64t;

// Blackwell packed dual-FMA: d.lo = a.lo*b.lo+c.lo ; d.hi = a.hi*b.hi+c.hi
__device__ __forceinline__ u64t ffma2(u64t a, u64t b, u64t c) {
    u64t d;
    asm("fma.rn.f32x2 %0, %1, %2, %3;" : "=l"(d) : "l"(a), "l"(b), "l"(c));
    return d;
}

// Scratch (allocation-free rule: __device__ globals)
__device__ float g_QC[NB*NH*NL*NHD];   // q + content_bias, [b,h,l,hd]
__device__ float g_QP[NB*NH*NL*NHD];   // q + position_bias
__device__ float g_Kt[NB*NH*NL*NHD];   // k, [b,h,l,hd]
__device__ float g_Vt[NB*NH*NL*NHD];   // v, [b,h,l,hd]
__device__ float g_PT[NB*NH*NP*NHD];   // pos projected, transposed: [b,h,p,hd]
__device__ float g_CTX[NB*NL*ND];      // attention output, [b,l,h*64+hd]

// ---------------------------------------------------------------------------
// fp32 SGEMM with packed f32x2 FMA micro-kernel.
// C[m,n] = sum_k A[m,k]*Bw[n,k] (+bias), K=1024 fixed.
// BM=BN=128, BK=16, 256 threads, 8x8 micro-tile as 8x4 packed pairs.
// A values duplicated in smem so broadcast pairs {a,a} load as single b64.
// ---------------------------------------------------------------------------
template<int EPI>
__global__ void __launch_bounds__(256, 2)
sgemm_k(const float* __restrict__ A, const float* __restrict__ Bw,
        int M, int N,
        const float* __restrict__ bias,
        const float* __restrict__ cbias, const float* __restrict__ pbias,
        float* __restrict__ out)
{
    __shared__ float As2[16][256];   // duplicated: As2[k][2r]=As2[k][2r+1]=A
    __shared__ float Bs[16][128];
    const int K = 1024;
    int t  = threadIdx.x;
    int tx = t & 15, ty = t >> 4;
    int m0 = blockIdx.y * 128, n0 = blockIdx.x * 128;
    int lr = t >> 2;          // 0..63
    int lc = (t & 3) << 2;    // 0,4,8,12

    u64t acc[8][4];
#pragma unroll
    for (int r = 0; r < 8; r++)
#pragma unroll
        for (int cp = 0; cp < 4; cp++) acc[r][cp] = 0ull;

    for (int kt = 0; kt < K; kt += 16) {
#pragma unroll
        for (int u = 0; u < 2; u++) {
            int row = lr + (u << 6);
            int m = m0 + row;
            float4 va = make_float4(0.f, 0.f, 0.f, 0.f);
            if (m < M) va = *(const float4*)(A + (size_t)m * K + kt + lc);
            *(float2*)&As2[lc + 0][2 * row] = make_float2(va.x, va.x);
            *(float2*)&As2[lc + 1][2 * row] = make_float2(va.y, va.y);
            *(float2*)&As2[lc + 2][2 * row] = make_float2(va.z, va.z);
            *(float2*)&As2[lc + 3][2 * row] = make_float2(va.w, va.w);
            int n = n0 + row;
            float4 vb = make_float4(0.f, 0.f, 0.f, 0.f);
            if (n < N) vb = *(const float4*)(Bw + (size_t)n * K + kt + lc);
            Bs[lc + 0][row] = vb.x; Bs[lc + 1][row] = vb.y;
            Bs[lc + 2][row] = vb.z; Bs[lc + 3][row] = vb.w;
        }
        __syncthreads();
#pragma unroll
        for (int k = 0; k < 16; k++) {
            ulonglong2 A0 = *(const ulonglong2*)&As2[k][ty * 16];
            ulonglong2 A1 = *(const ulonglong2*)&As2[k][ty * 16 + 4];
            ulonglong2 A2 = *(const ulonglong2*)&As2[k][ty * 16 + 8];
            ulonglong2 A3 = *(const ulonglong2*)&As2[k][ty * 16 + 12];
            ulonglong2 B0 = *(const ulonglong2*)&Bs[k][tx * 8];
            ulonglong2 B1 = *(const ulonglong2*)&Bs[k][tx * 8 + 4];
            u64t av[8] = {A0.x, A0.y, A1.x, A1.y, A2.x, A2.y, A3.x, A3.y};
            u64t bv[4] = {B0.x, B0.y, B1.x, B1.y};
#pragma unroll
            for (int r = 0; r < 8; r++)
#pragma unroll
                for (int cp = 0; cp < 4; cp++)
                    acc[r][cp] = ffma2(av[r], bv[cp], acc[r][cp]);
        }
        __syncthreads();
    }

#pragma unroll
    for (int r = 0; r < 8; r++) {
        int m = m0 + ty * 8 + r;
        if (m >= M) continue;
        float cv[8];
#pragma unroll
        for (int cp = 0; cp < 4; cp++) {
            float2 f = *(float2*)&acc[r][cp];
            cv[cp * 2] = f.x; cv[cp * 2 + 1] = f.y;
        }
        if (EPI == 0) {
            // QKV: m=(b,l), n in [0,3072): part,h,hd. Scatter to QC/QP/K/V.
            int b_ = m / NL, l = m - b_ * NL;
#pragma unroll
            for (int c = 0; c < 8; c++) {
                int n = n0 + tx * 8 + c;
                float v = cv[c] + bias[n];
                int part = n >> 10, c1 = n & 1023;
                int hh = c1 >> 6, hd = c1 & 63;
                size_t o = ((((size_t)b_ * NH + hh) * NL + l) << 6) + hd;
                if (part == 0) {
                    g_QC[o] = v + cbias[c1];
                    g_QP[o] = v + pbias[c1];
                } else if (part == 1) {
                    g_Kt[o] = v;
                } else {
                    g_Vt[o] = v;
                }
            }
        } else if (EPI == 1) {
            // POS: m = p, n = (b*H+h)*64+hd, bias indexed by p.
            float bm = bias[m];
#pragma unroll
            for (int c = 0; c < 8; c++) {
                int n = n0 + tx * 8 + c;
                float v = cv[c] + bm;
                int bh = n >> 6, hd = n & 63;
                g_PT[((((size_t)bh) << 10) + m) * 64 + hd] = v;
            }
        } else {
            // OUT: plain vectorized store
            float* op = out + (size_t)m * ND + n0 + tx * 8;
            *(float4*)op       = make_float4(cv[0], cv[1], cv[2], cv[3]);
            *(float4*)(op + 4) = make_float4(cv[4], cv[5], cv[6], cv[7]);
        }
    }
}

// ---------------------------------------------------------------------------
// Fused attention per (b,h,i-tile of 32 queries):
//  score[i,j] = qc_i . k_j + qp_i . posT[j-i+512]   (rel-shift as index map)
//  full-row softmax (scale + mask), then ctx = softmax(scores) @ V
// Scores stored as fp16 -> smem 92.5KB -> 2 CTAs/SM.
// ---------------------------------------------------------------------------
__global__ void __launch_bounds__(256, 2)
attn_k(const unsigned char* __restrict__ mask, float* __restrict__ ctx)
{
    extern __shared__ float smf[];
    float* sQC  = smf;                 // [64][33]  q+cb transposed
    float* sQP  = sQC + 64 * 33;       // [64][33]  q+pb transposed
    float* sKV  = sQP + 64 * 33;       // [64][68]  K transposed / V direct
    float* sPb  = sKV + 64 * 68;       // [64][97]  pos band transposed
    float* sSum = sPb + 64 * 97;       // [32]
    __half* sSh = (__half*)(sSum + 32); // [32][520] score rows (fp16)

    int t  = threadIdx.x;
    int it = blockIdx.x, h = blockIdx.y, b = blockIdx.z;
    int i0 = it * 32;
    size_t bh = (size_t)b * NH + h;
    const float* QCg = g_QC + bh * NL * NHD;
    const float* QPg = g_QP + bh * NL * NHD;
    const float* Kg  = g_Kt + bh * NL * NHD;
    const float* Vg  = g_Vt + bh * NL * NHD;
    const float* Pg  = g_PT + bh * NP * NHD;

    // load query tiles (transposed, padded)
    for (int idx = t; idx < 2048; idx += 256) {
        int li = idx >> 6, hd = idx & 63;
        int i = i0 + li;
        float vq = 0.f, vp = 0.f;
        if (i < NL) { vq = QCg[i * 64 + hd]; vp = QPg[i * 64 + hd]; }
        sQC[hd * 33 + li] = vq;
        sQP[hd * 33 + li] = vp;
    }

    int tx = t & 15, ty = t >> 4;
    int li0 = ty << 1, lj0 = tx << 2;
    int bA = lj0 - li0 + 31;   // band index for (ii=0, jj=0); >= 1 always

    // ----- score phase -----
    for (int jt = 0; jt < 9; jt++) {
        int j0 = jt << 6;
        __syncthreads();   // protects q-load (jt=0) and sKV/sPb reuse (jt>0)
        for (int idx = t; idx < 4096; idx += 256) {
            int lj = idx >> 6, hd = idx & 63;
            int j = j0 + lj;
            sKV[hd * 68 + lj] = (j < NL) ? Kg[j * 64 + hd] : 0.f;
        }
        int base = j0 - i0 + 481;   // global pos index of band row 0
        for (int idx = t; idx < 6144; idx += 256) {
            int bi = idx >> 6, hd = idx & 63;
            int gi = base + bi;
            sPb[hd * 97 + bi] = ((unsigned)gi < (unsigned)NP) ? Pg[(size_t)gi * 64 + hd] : 0.f;
        }
        __syncthreads();

        float a00=0,a01=0,a02=0,a03=0,a10=0,a11=0,a12=0,a13=0;
#pragma unroll 8
        for (int k = 0; k < 64; k++) {
            float qc0 = sQC[k * 33 + li0];
            float qc1 = sQC[k * 33 + li0 + 1];
            float qp0 = sQP[k * 33 + li0];
            float qp1 = sQP[k * 33 + li0 + 1];
            float4 kv = *(const float4*)&sKV[k * 68 + lj0];
            const float* pr = &sPb[k * 97 + bA - 1];
            float f0 = pr[0], f1 = pr[1], f2 = pr[2], f3 = pr[3], f4 = pr[4];
            a00 += qc0 * kv.x; a01 += qc0 * kv.y; a02 += qc0 * kv.z; a03 += qc0 * kv.w;
            a10 += qc1 * kv.x; a11 += qc1 * kv.y; a12 += qc1 * kv.z; a13 += qc1 * kv.w;
            a00 += qp0 * f1;   a01 += qp0 * f2;   a02 += qp0 * f3;   a03 += qp0 * f4;
            a10 += qp1 * f0;   a11 += qp1 * f1;   a12 += qp1 * f2;   a13 += qp1 * f3;
        }
        int jb = j0 + lj0;
        __half* s0 = &sSh[li0 * 520];
        __half* s1 = &sSh[(li0 + 1) * 520];
        if (jb + 0 < NL) { s0[jb + 0] = __float2half_rn(a00); s1[jb + 0] = __float2half_rn(a10); }
        if (jb + 1 < NL) { s0[jb + 1] = __float2half_rn(a01); s1[jb + 1] = __float2half_rn(a11); }
        if (jb + 2 < NL) { s0[jb + 2] = __float2half_rn(a02); s1[jb + 2] = __float2half_rn(a12); }
        if (jb + 3 < NL) { s0[jb + 3] = __float2half_rn(a03); s1[jb + 3] = __float2half_rn(a13); }
    }
    __syncthreads();

    // ----- softmax (warp per row-group); raw scores kept, exp written back --
    int w = t >> 5, lane = t & 31;
    for (int li = w; li < 32; li += 8) {
        int i = i0 + li;
        if (i >= NL) { if (lane == 0) sSum[li] = 1.f; continue; }
        const unsigned char* mrow = mask + ((size_t)b * NL + i) * NL;
        __half* srow = &sSh[li * 520];
        float mx = -3.4028235e38f;
        for (int j = lane; j < NL; j += 32) {
            float v = __half2float(srow[j]) * 0.125f;   // scale = 1/sqrt(64)
            if (mrow[j]) v = -3.4028235e38f;
            mx = fmaxf(mx, v);
        }
#pragma unroll
        for (int o = 16; o > 0; o >>= 1) mx = fmaxf(mx, __shfl_xor_sync(0xffffffffu, mx, o));
        float s = 0.f;
        for (int j = lane; j < NL; j += 32) {
            float v = __half2float(srow[j]) * 0.125f;
            if (mrow[j]) v = -3.4028235e38f;
            float e = __expf(v - mx);
            srow[j] = __float2half_rn(e);
            s += e;
        }
#pragma unroll
        for (int o = 16; o > 0; o >>= 1) s += __shfl_xor_sync(0xffffffffu, s, o);
        if (lane == 0) sSum[li] = s;
    }

    // ----- AV phase -----
    float o00=0,o01=0,o02=0,o03=0,o10=0,o11=0,o12=0,o13=0;
    for (int jt = 0; jt < 9; jt++) {
        int j0 = jt << 6;
        int jmax = NL - j0; if (jmax > 64) jmax = 64;
        __syncthreads();   // first iter also fences softmax completion
        for (int idx = t; idx < 4096; idx += 256) {
            int lj = idx >> 6, hd = idx & 63;
            int j = j0 + lj;
            sKV[idx] = (j < NL) ? Vg[j * 64 + hd] : 0.f;   // [lj][hd] direct
        }
        __syncthreads();
        const __half2* h0 = (const __half2*)&sSh[li0 * 520 + j0];
        const __half2* h1 = (const __half2*)&sSh[(li0 + 1) * 520 + j0];
        int jp2 = jmax >> 1;
        for (int jp = 0; jp < jp2; jp++) {
            float2 w0 = __half22float2(h0[jp]);
            float2 w1 = __half22float2(h1[jp]);
            float4 va = *(const float4*)&sKV[(2 * jp) * 64 + lj0];
            float4 vb = *(const float4*)&sKV[(2 * jp + 1) * 64 + lj0];
            o00 += w0.x * va.x; o01 += w0.x * va.y; o02 += w0.x * va.z; o03 += w0.x * va.w;
            o10 += w1.x * va.x; o11 += w1.x * va.y; o12 += w1.x * va.z; o13 += w1.x * va.w;
            o00 += w0.y * vb.x; o01 += w0.y * vb.y; o02 += w0.y * vb.z; o03 += w0.y * vb.w;
            o10 += w1.y * vb.x; o11 += w1.y * vb.y; o12 += w1.y * vb.z; o13 += w1.y * vb.w;
        }
        if (jmax & 1) {
            int j = jmax - 1;
            float w0 = __half2float(sSh[li0 * 520 + j0 + j]);
            float w1 = __half2float(sSh[(li0 + 1) * 520 + j0 + j]);
            float4 va = *(const float4*)&sKV[j * 64 + lj0];
            o00 += w0 * va.x; o01 += w0 * va.y; o02 += w0 * va.z; o03 += w0 * va.w;
            o10 += w1 * va.x; o11 += w1 * va.y; o12 += w1 * va.z; o13 += w1 * va.w;
        }
    }
    int ia = i0 + li0, ib = ia + 1;
    if (ia < NL) {
        float inv = 1.f / sSum[li0];
        float4 r = make_float4(o00 * inv, o01 * inv, o02 * inv, o03 * inv);
        *(float4*)&ctx[((size_t)b * NL + ia) * ND + h * 64 + lj0] = r;
    }
    if (ib < NL) {
        float inv = 1.f / sSum[li0 + 1];
        float4 r = make_float4(o10 * inv, o11 * inv, o12 * inv, o13 * inv);
        *(float4*)&ctx[((size_t)b * NL + ib) * ND + h * 64 + lj0] = r;
    }
}

// ---------------------------------------------------------------------------
extern "C" void kernel_launch(void* const* d_in, const int* in_sizes, int n_in,
                              void* d_out, int out_size)
{
    const float* x     = (const float*)d_in[0];
    const float* pe    = (const float*)d_in[1];
    const unsigned char* mask = (const unsigned char*)d_in[2];
    const float* qkv_w = (const float*)d_in[3];
    const float* qkv_b = (const float*)d_in[4];
    const float* pos_w = (const float*)d_in[5];
    const float* pos_b = (const float*)d_in[6];
    const float* out_w = (const float*)d_in[7];
    const float* out_b = (const float*)d_in[8];
    const float* cbias = (const float*)d_in[9];
    const float* pbias = (const float*)d_in[10];
    float* out = (float*)d_out;

    float* ctxp = nullptr;
    cudaGetSymbolAddress((void**)&ctxp, g_CTX);

    const int M1 = NB * NL;                 // 8208
    const int ATTN_SMEM = (64*33*2 + 64*68 + 64*97 + 32) * 4 + 32 * 520 * 2;  // 92544 B
    cudaFuncSetAttribute(attn_k, cudaFuncAttributeMaxDynamicSharedMemorySize, ATTN_SMEM);

    dim3 blk(256);
    // QKV projection + scatter (q+biases, k, v)
    sgemm_k<0><<<dim3(3072 / 128, (M1 + 127) / 128), blk>>>(
        x, qkv_w, M1, 3072, qkv_b, cbias, pbias, nullptr);
    // pos projection (independent of QKV)
    sgemm_k<1><<<dim3(16384 / 128, 1024 / 128), blk>>>(
        pos_w, pe, 1024, 16384, pos_b, nullptr, nullptr, nullptr);
    // fused content+position scores, softmax, AV
    attn_k<<<dim3(17, NH, NB), blk, ATTN_SMEM>>>(mask, ctxp);
    // output projection
    sgemm_k<2><<<dim3(1024 / 128, (M1 + 127) / 128), blk>>>(
        ctxp, out_w, M1, 1024, out_b, nullptr, nullptr, out);
}

// round 3
// speedup vs baseline: 2.1074x; 1.8814x over previous
#include <cuda_runtime.h>
#include <cuda_fp16.h>
#include <math.h>

#define NB 16
#define NH 16
#define NHD 64
#define ND 1024
#define NL 513
#define NP 1024

// Scratch (allocation-free rule: __device__ globals)
__device__ float g_QC[NB*NH*NL*NHD];   // q + content_bias, [b,h,l,hd]
__device__ float g_QP[NB*NH*NL*NHD];   // q + position_bias
__device__ float g_Kt[NB*NH*NL*NHD];   // k, [b,h,l,hd]
__device__ float g_Vt[NB*NH*NL*NHD];   // v, [b,h,l,hd]
__device__ float g_PT[NB*NH*NP*NHD];   // pos projected, transposed: [b,h,p,hd]
__device__ float g_CTX[NB*NL*ND];      // attention output, [b,l,h*64+hd]

__device__ __forceinline__ unsigned cvt_tf32(float f) {
    unsigned u;
    asm("cvt.rna.tf32.f32 %0, %1;" : "=r"(u) : "f"(f));
    return u;
}

__device__ __forceinline__ void mma_tf32(float* d, const uint4& a, const uint2& b) {
    asm volatile(
        "mma.sync.aligned.m16n8k8.row.col.f32.tf32.tf32.f32 "
        "{%0,%1,%2,%3}, {%4,%5,%6,%7}, {%8,%9}, {%0,%1,%2,%3};"
        : "+f"(d[0]), "+f"(d[1]), "+f"(d[2]), "+f"(d[3])
        : "r"(a.x), "r"(a.y), "r"(a.z), "r"(a.w), "r"(b.x), "r"(b.y));
}

// ---------------------------------------------------------------------------
// tf32 tensor-core GEMM: C[m,n] = sum_k A[m,k]*Bw[n,k] (+epilogue), K=1024.
// BM=BN=128, BK=32, 256 threads = 8 warps as 2(M)x4(N) grid of 64x32 tiles.
// Smem stores mma fragments directly: compute-phase loads are one LDS.128 (A)
// or LDS.64 (B) per tile, conflict-free.
//   sA layout: [ks(4)][mt(8)][lane(32) x 4 frags], strides 1060/132 (16B align)
//   sB layout: [ks(4)][nt(16)][lane(32) x 2 frags], strides 1026/64 (8B align)
// ---------------------------------------------------------------------------
template<int EPI>
__global__ void __launch_bounds__(256, 2)
gemm_tf32(const float* __restrict__ A, const float* __restrict__ Bw,
          int M, int N,
          const float* __restrict__ bias,
          const float* __restrict__ cbias, const float* __restrict__ pbias,
          float* __restrict__ out)
{
    const int K = 1024;
    __shared__ unsigned sA[4240];
    __shared__ unsigned sB[4104];

    int t    = threadIdx.x;
    int lane = t & 31, w = t >> 5;
    int warpM = w & 1, warpN = w >> 1;
    int m0 = blockIdx.y * 128, n0 = blockIdx.x * 128;

    int lrow = t >> 3;        // 0..31
    int lkq  = t & 7;         // float4 index along k (k' = lkq*4..lkq*4+3)
    int ksL  = lkq >> 1;
    int frp  = lkq & 1;       // k'>=4 within the 8-wide kstep?

    float acc[4][4][4];
#pragma unroll
    for (int i = 0; i < 4; i++)
#pragma unroll
        for (int j = 0; j < 4; j++)
#pragma unroll
            for (int r = 0; r < 4; r++) acc[i][j][r] = 0.f;

    for (int kt = 0; kt < K; kt += 32) {
#pragma unroll
        for (int u = 0; u < 4; u++) {
            int ml = lrow + u * 32;
            int gm = m0 + ml;
            float4 va = make_float4(0.f, 0.f, 0.f, 0.f);
            if (gm < M) va = *(const float4*)(A + (size_t)gm * K + kt + lkq * 4);
            int mt = ml >> 4, mp = ml & 15;
            int fr = frp * 2 + (mp >> 3);
            unsigned ba = ksL * 1060 + mt * 132 + (mp & 7) * 16 + fr;
            sA[ba + 0]  = cvt_tf32(va.x);
            sA[ba + 4]  = cvt_tf32(va.y);
            sA[ba + 8]  = cvt_tf32(va.z);
            sA[ba + 12] = cvt_tf32(va.w);

            int nl = ml;   // N tiles are always full (N % 128 == 0)
            float4 vb = *(const float4*)(Bw + (size_t)(n0 + nl) * K + kt + lkq * 4);
            int nt = nl >> 3, np = nl & 7;
            unsigned bb = ksL * 1026 + nt * 64 + np * 8 + frp;
            sB[bb + 0] = cvt_tf32(vb.x);
            sB[bb + 2] = cvt_tf32(vb.y);
            sB[bb + 4] = cvt_tf32(vb.z);
            sB[bb + 6] = cvt_tf32(vb.w);
        }
        __syncthreads();

#pragma unroll
        for (int ks = 0; ks < 4; ks++) {
            uint4 av[4];
            uint2 bv[4];
#pragma unroll
            for (int i = 0; i < 4; i++)
                av[i] = *(const uint4*)&sA[ks * 1060 + (warpM * 4 + i) * 132 + lane * 4];
#pragma unroll
            for (int j = 0; j < 4; j++)
                bv[j] = *(const uint2*)&sB[ks * 1026 + (warpN * 4 + j) * 64 + lane * 2];
#pragma unroll
            for (int i = 0; i < 4; i++)
#pragma unroll
                for (int j = 0; j < 4; j++)
                    mma_tf32(acc[i][j], av[i], bv[j]);
        }
        __syncthreads();
    }

    // ----- epilogue: element (i,j,r): m = base + i*16 + (r>>1)*8, n = base + j*8 + (r&1)
    int mb = m0 + warpM * 64 + (lane >> 2);
    int nb = n0 + warpN * 32 + (lane & 3) * 2;
#pragma unroll
    for (int i = 0; i < 4; i++) {
#pragma unroll
        for (int rr = 0; rr < 2; rr++) {
            int m = mb + i * 16 + rr * 8;
            if (m >= M) continue;
            if (EPI == 0) {
                int b_ = m / NL, l = m - b_ * NL;
#pragma unroll
                for (int j = 0; j < 4; j++) {
#pragma unroll
                    for (int e = 0; e < 2; e++) {
                        int n = nb + j * 8 + e;
                        float v = acc[i][j][rr * 2 + e] + bias[n];
                        int part = n >> 10, c1 = n & 1023;
                        int hh = c1 >> 6, hd = c1 & 63;
                        size_t o = ((((size_t)b_ * NH + hh) * NL + l) << 6) + hd;
                        if (part == 0) {
                            g_QC[o] = v + cbias[c1];
                            g_QP[o] = v + pbias[c1];
                        } else if (part == 1) {
                            g_Kt[o] = v;
                        } else {
                            g_Vt[o] = v;
                        }
                    }
                }
            } else if (EPI == 1) {
                float bm = bias[m];
#pragma unroll
                for (int j = 0; j < 4; j++) {
#pragma unroll
                    for (int e = 0; e < 2; e++) {
                        int n = nb + j * 8 + e;
                        float v = acc[i][j][rr * 2 + e] + bm;
                        int bh = n >> 6, hd = n & 63;
                        g_PT[((((size_t)bh) << 10) + m) * 64 + hd] = v;
                    }
                }
            } else {
#pragma unroll
                for (int j = 0; j < 4; j++) {
                    int n = nb + j * 8;
                    float2 st;
                    st.x = acc[i][j][rr * 2 + 0] + bias[n];
                    st.y = acc[i][j][rr * 2 + 1] + bias[n + 1];
                    *(float2*)(out + (size_t)m * ND + n) = st;
                }
            }
        }
    }
}

// ---------------------------------------------------------------------------
// Fused attention per (b,h,i-tile of 32 queries):
//  score[i,j] = qc_i . k_j + qp_i . posT[j-i+512]   (rel-shift as index map)
//  full-row softmax (scale + mask), then ctx = softmax(scores) @ V
// Scores stored as fp16 -> smem 92.5KB -> 2 CTAs/SM.
// ---------------------------------------------------------------------------
__global__ void __launch_bounds__(256, 2)
attn_k(const unsigned char* __restrict__ mask, float* __restrict__ ctx)
{
    extern __shared__ float smf[];
    float* sQC  = smf;                 // [64][33]  q+cb transposed
    float* sQP  = sQC + 64 * 33;       // [64][33]  q+pb transposed
    float* sKV  = sQP + 64 * 33;       // [64][68]  K transposed / V direct
    float* sPb  = sKV + 64 * 68;       // [64][97]  pos band transposed
    float* sSum = sPb + 64 * 97;       // [32]
    __half* sSh = (__half*)(sSum + 32); // [32][520] score rows (fp16)

    int t  = threadIdx.x;
    int it = blockIdx.x, h = blockIdx.y, b = blockIdx.z;
    int i0 = it * 32;
    size_t bh = (size_t)b * NH + h;
    const float* QCg = g_QC + bh * NL * NHD;
    const float* QPg = g_QP + bh * NL * NHD;
    const float* Kg  = g_Kt + bh * NL * NHD;
    const float* Vg  = g_Vt + bh * NL * NHD;
    const float* Pg  = g_PT + bh * NP * NHD;

    // load query tiles (transposed, padded)
    for (int idx = t; idx < 2048; idx += 256) {
        int li = idx >> 6, hd = idx & 63;
        int i = i0 + li;
        float vq = 0.f, vp = 0.f;
        if (i < NL) { vq = QCg[i * 64 + hd]; vp = QPg[i * 64 + hd]; }
        sQC[hd * 33 + li] = vq;
        sQP[hd * 33 + li] = vp;
    }

    int tx = t & 15, ty = t >> 4;
    int li0 = ty << 1, lj0 = tx << 2;
    int bA = lj0 - li0 + 31;   // band index for (ii=0, jj=0); >= 1 always

    // ----- score phase -----
    for (int jt = 0; jt < 9; jt++) {
        int j0 = jt << 6;
        __syncthreads();   // protects q-load (jt=0) and sKV/sPb reuse (jt>0)
        for (int idx = t; idx < 4096; idx += 256) {
            int lj = idx >> 6, hd = idx & 63;
            int j = j0 + lj;
            sKV[hd * 68 + lj] = (j < NL) ? Kg[j * 64 + hd] : 0.f;
        }
        int base = j0 - i0 + 481;   // global pos index of band row 0
        for (int idx = t; idx < 6144; idx += 256) {
            int bi = idx >> 6, hd = idx & 63;
            int gi = base + bi;
            sPb[hd * 97 + bi] = ((unsigned)gi < (unsigned)NP) ? Pg[(size_t)gi * 64 + hd] : 0.f;
        }
        __syncthreads();

        float a00=0,a01=0,a02=0,a03=0,a10=0,a11=0,a12=0,a13=0;
#pragma unroll 8
        for (int k = 0; k < 64; k++) {
            float qc0 = sQC[k * 33 + li0];
            float qc1 = sQC[k * 33 + li0 + 1];
            float qp0 = sQP[k * 33 + li0];
            float qp1 = sQP[k * 33 + li0 + 1];
            float4 kv = *(const float4*)&sKV[k * 68 + lj0];
            const float* pr = &sPb[k * 97 + bA - 1];
            float f0 = pr[0], f1 = pr[1], f2 = pr[2], f3 = pr[3], f4 = pr[4];
            a00 += qc0 * kv.x; a01 += qc0 * kv.y; a02 += qc0 * kv.z; a03 += qc0 * kv.w;
            a10 += qc1 * kv.x; a11 += qc1 * kv.y; a12 += qc1 * kv.z; a13 += qc1 * kv.w;
            a00 += qp0 * f1;   a01 += qp0 * f2;   a02 += qp0 * f3;   a03 += qp0 * f4;
            a10 += qp1 * f0;   a11 += qp1 * f1;   a12 += qp1 * f2;   a13 += qp1 * f3;
        }
        int jb = j0 + lj0;
        __half* s0 = &sSh[li0 * 520];
        __half* s1 = &sSh[(li0 + 1) * 520];
        if (jb + 0 < NL) { s0[jb + 0] = __float2half_rn(a00); s1[jb + 0] = __float2half_rn(a10); }
        if (jb + 1 < NL) { s0[jb + 1] = __float2half_rn(a01); s1[jb + 1] = __float2half_rn(a11); }
        if (jb + 2 < NL) { s0[jb + 2] = __float2half_rn(a02); s1[jb + 2] = __float2half_rn(a12); }
        if (jb + 3 < NL) { s0[jb + 3] = __float2half_rn(a03); s1[jb + 3] = __float2half_rn(a13); }
    }
    __syncthreads();

    // ----- softmax (warp per row-group); raw scores kept, exp written back --
    int w = t >> 5, lane = t & 31;
    for (int li = w; li < 32; li += 8) {
        int i = i0 + li;
        if (i >= NL) { if (lane == 0) sSum[li] = 1.f; continue; }
        const unsigned char* mrow = mask + ((size_t)b * NL + i) * NL;
        __half* srow = &sSh[li * 520];
        float mx = -3.4028235e38f;
        for (int j = lane; j < NL; j += 32) {
            float v = __half2float(srow[j]) * 0.125f;   // scale = 1/sqrt(64)
            if (mrow[j]) v = -3.4028235e38f;
            mx = fmaxf(mx, v);
        }
#pragma unroll
        for (int o = 16; o > 0; o >>= 1) mx = fmaxf(mx, __shfl_xor_sync(0xffffffffu, mx, o));
        float s = 0.f;
        for (int j = lane; j < NL; j += 32) {
            float v = __half2float(srow[j]) * 0.125f;
            if (mrow[j]) v = -3.4028235e38f;
            float e = __expf(v - mx);
            srow[j] = __float2half_rn(e);
            s += e;
        }
#pragma unroll
        for (int o = 16; o > 0; o >>= 1) s += __shfl_xor_sync(0xffffffffu, s, o);
        if (lane == 0) sSum[li] = s;
    }

    // ----- AV phase -----
    float o00=0,o01=0,o02=0,o03=0,o10=0,o11=0,o12=0,o13=0;
    for (int jt = 0; jt < 9; jt++) {
        int j0 = jt << 6;
        int jmax = NL - j0; if (jmax > 64) jmax = 64;
        __syncthreads();   // first iter also fences softmax completion
        for (int idx = t; idx < 4096; idx += 256) {
            int lj = idx >> 6, hd = idx & 63;
            int j = j0 + lj;
            sKV[idx] = (j < NL) ? Vg[j * 64 + hd] : 0.f;   // [lj][hd] direct
        }
        __syncthreads();
        const __half2* h0 = (const __half2*)&sSh[li0 * 520 + j0];
        const __half2* h1 = (const __half2*)&sSh[(li0 + 1) * 520 + j0];
        int jp2 = jmax >> 1;
        for (int jp = 0; jp < jp2; jp++) {
            float2 w0 = __half22float2(h0[jp]);
            float2 w1 = __half22float2(h1[jp]);
            float4 va = *(const float4*)&sKV[(2 * jp) * 64 + lj0];
            float4 vb = *(const float4*)&sKV[(2 * jp + 1) * 64 + lj0];
            o00 += w0.x * va.x; o01 += w0.x * va.y; o02 += w0.x * va.z; o03 += w0.x * va.w;
            o10 += w1.x * va.x; o11 += w1.x * va.y; o12 += w1.x * va.z; o13 += w1.x * va.w;
            o00 += w0.y * vb.x; o01 += w0.y * vb.y; o02 += w0.y * vb.z; o03 += w0.y * vb.w;
            o10 += w1.y * vb.x; o11 += w1.y * vb.y; o12 += w1.y * vb.z; o13 += w1.y * vb.w;
        }
        if (jmax & 1) {
            int j = jmax - 1;
            float w0 = __half2float(sSh[li0 * 520 + j0 + j]);
            float w1 = __half2float(sSh[(li0 + 1) * 520 + j0 + j]);
            float4 va = *(const float4*)&sKV[j * 64 + lj0];
            o00 += w0 * va.x; o01 += w0 * va.y; o02 += w0 * va.z; o03 += w0 * va.w;
            o10 += w1 * va.x; o11 += w1 * va.y; o12 += w1 * va.z; o13 += w1 * va.w;
        }
    }
    int ia = i0 + li0, ib = ia + 1;
    if (ia < NL) {
        float inv = 1.f / sSum[li0];
        float4 r = make_float4(o00 * inv, o01 * inv, o02 * inv, o03 * inv);
        *(float4*)&ctx[((size_t)b * NL + ia) * ND + h * 64 + lj0] = r;
    }
    if (ib < NL) {
        float inv = 1.f / sSum[li0 + 1];
        float4 r = make_float4(o10 * inv, o11 * inv, o12 * inv, o13 * inv);
        *(float4*)&ctx[((size_t)b * NL + ib) * ND + h * 64 + lj0] = r;
    }
}

// ---------------------------------------------------------------------------
extern "C" void kernel_launch(void* const* d_in, const int* in_sizes, int n_in,
                              void* d_out, int out_size)
{
    const float* x     = (const float*)d_in[0];
    const float* pe    = (const float*)d_in[1];
    const unsigned char* mask = (const unsigned char*)d_in[2];
    const float* qkv_w = (const float*)d_in[3];
    const float* qkv_b = (const float*)d_in[4];
    const float* pos_w = (const float*)d_in[5];
    const float* pos_b = (const float*)d_in[6];
    const float* out_w = (const float*)d_in[7];
    const float* out_b = (const float*)d_in[8];
    const float* cbias = (const float*)d_in[9];
    const float* pbias = (const float*)d_in[10];
    float* out = (float*)d_out;

    float* ctxp = nullptr;
    cudaGetSymbolAddress((void**)&ctxp, g_CTX);

    const int M1 = NB * NL;                 // 8208
    const int ATTN_SMEM = (64*33*2 + 64*68 + 64*97 + 32) * 4 + 32 * 520 * 2;  // 92544 B
    cudaFuncSetAttribute(attn_k, cudaFuncAttributeMaxDynamicSharedMemorySize, ATTN_SMEM);

    dim3 blk(256);
    // QKV projection + scatter (q+biases, k, v)
    gemm_tf32<0><<<dim3(3072 / 128, (M1 + 127) / 128), blk>>>(
        x, qkv_w, M1, 3072, qkv_b, cbias, pbias, nullptr);
    // pos projection (independent of QKV)
    gemm_tf32<1><<<dim3(16384 / 128, 1024 / 128), blk>>>(
        pos_w, pe, 1024, 16384, pos_b, nullptr, nullptr, nullptr);
    // fused content+position scores, softmax, AV
    attn_k<<<dim3(17, NH, NB), blk, ATTN_SMEM>>>(mask, ctxp);
    // output projection
    gemm_tf32<2><<<dim3(1024 / 128, (M1 + 127) / 128), blk>>>(
        ctxp, out_w, M1, 1024, out_b, nullptr, nullptr, out);
}

// round 5
// speedup vs baseline: 3.7654x; 1.7867x over previous
#include <cuda_runtime.h>
#include <cuda_fp16.h>
#include <math.h>

#define NB 16
#define NH 16
#define NHD 64
#define ND 1024
#define NL 513
#define NP 1024

// Scratch (allocation-free rule: __device__ globals)
__device__ float g_QC[NB*NH*NL*NHD];   // q + content_bias, [b,h,l,hd]
__device__ float g_QP[NB*NH*NL*NHD];   // q + position_bias
__device__ float g_Kt[NB*NH*NL*NHD];   // k, [b,h,l,hd]
__device__ float g_Vt[NB*NH*NL*NHD];   // v, [b,h,l,hd]
__device__ float g_PT[NB*NH*NP*NHD];   // pos projected, transposed: [b,h,p,hd]
__device__ float g_CTX[NB*NL*ND];      // attention output, [b,l,h*64+hd]

__device__ __forceinline__ unsigned cvt_tf32(float f) {
    unsigned u;
    asm("cvt.rna.tf32.f32 %0, %1;" : "=r"(u) : "f"(f));
    return u;
}

__device__ __forceinline__ void mma_tf32(float* d, const uint4& a, const uint2& b) {
    asm volatile(
        "mma.sync.aligned.m16n8k8.row.col.f32.tf32.tf32.f32 "
        "{%0,%1,%2,%3}, {%4,%5,%6,%7}, {%8,%9}, {%0,%1,%2,%3};"
        : "+f"(d[0]), "+f"(d[1]), "+f"(d[2]), "+f"(d[3])
        : "r"(a.x), "r"(a.y), "r"(a.z), "r"(a.w), "r"(b.x), "r"(b.y));
}

__device__ __forceinline__ void mma_f16(float* d, const uint4& a, const uint2& b) {
    asm volatile(
        "mma.sync.aligned.m16n8k16.row.col.f32.f16.f16.f32 "
        "{%0,%1,%2,%3}, {%4,%5,%6,%7}, {%8,%9}, {%0,%1,%2,%3};"
        : "+f"(d[0]), "+f"(d[1]), "+f"(d[2]), "+f"(d[3])
        : "r"(a.x), "r"(a.y), "r"(a.z), "r"(a.w), "r"(b.x), "r"(b.y));
}

__device__ __forceinline__ unsigned pkh2(float x, float y) {
    __half2 h = __floats2half2_rn(x, y);
    return *(unsigned*)&h;
}

// ---------------------------------------------------------------------------
// tf32 tensor-core GEMM (unchanged): C = A @ Bw^T (+epilogue)
// ---------------------------------------------------------------------------
template<int EPI>
__global__ void __launch_bounds__(256, 2)
gemm_tf32(const float* __restrict__ A, const float* __restrict__ Bw,
          int M, int N,
          const float* __restrict__ bias,
          const float* __restrict__ cbias, const float* __restrict__ pbias,
          float* __restrict__ out)
{
    const int K = 1024;
    __shared__ unsigned sA[4240];
    __shared__ unsigned sB[4104];

    int t    = threadIdx.x;
    int lane = t & 31, w = t >> 5;
    int warpM = w & 1, warpN = w >> 1;
    int m0 = blockIdx.y * 128, n0 = blockIdx.x * 128;

    int lrow = t >> 3;
    int lkq  = t & 7;
    int ksL  = lkq >> 1;
    int frp  = lkq & 1;

    float acc[4][4][4];
#pragma unroll
    for (int i = 0; i < 4; i++)
#pragma unroll
        for (int j = 0; j < 4; j++)
#pragma unroll
            for (int r = 0; r < 4; r++) acc[i][j][r] = 0.f;

    for (int kt = 0; kt < K; kt += 32) {
#pragma unroll
        for (int u = 0; u < 4; u++) {
            int ml = lrow + u * 32;
            int gm = m0 + ml;
            float4 va = make_float4(0.f, 0.f, 0.f, 0.f);
            if (gm < M) va = *(const float4*)(A + (size_t)gm * K + kt + lkq * 4);
            int mt = ml >> 4, mp = ml & 15;
            int fr = frp * 2 + (mp >> 3);
            unsigned ba = ksL * 1060 + mt * 132 + (mp & 7) * 16 + fr;
            sA[ba + 0]  = cvt_tf32(va.x);
            sA[ba + 4]  = cvt_tf32(va.y);
            sA[ba + 8]  = cvt_tf32(va.z);
            sA[ba + 12] = cvt_tf32(va.w);

            int nl = ml;
            float4 vb = *(const float4*)(Bw + (size_t)(n0 + nl) * K + kt + lkq * 4);
            int nt = nl >> 3, np = nl & 7;
            unsigned bb = ksL * 1026 + nt * 64 + np * 8 + frp;
            sB[bb + 0] = cvt_tf32(vb.x);
            sB[bb + 2] = cvt_tf32(vb.y);
            sB[bb + 4] = cvt_tf32(vb.z);
            sB[bb + 6] = cvt_tf32(vb.w);
        }
        __syncthreads();

#pragma unroll
        for (int ks = 0; ks < 4; ks++) {
            uint4 av[4];
            uint2 bv[4];
#pragma unroll
            for (int i = 0; i < 4; i++)
                av[i] = *(const uint4*)&sA[ks * 1060 + (warpM * 4 + i) * 132 + lane * 4];
#pragma unroll
            for (int j = 0; j < 4; j++)
                bv[j] = *(const uint2*)&sB[ks * 1026 + (warpN * 4 + j) * 64 + lane * 2];
#pragma unroll
            for (int i = 0; i < 4; i++)
#pragma unroll
                for (int j = 0; j < 4; j++)
                    mma_tf32(acc[i][j], av[i], bv[j]);
        }
        __syncthreads();
    }

    int mb = m0 + warpM * 64 + (lane >> 2);
    int nb = n0 + warpN * 32 + (lane & 3) * 2;
#pragma unroll
    for (int i = 0; i < 4; i++) {
#pragma unroll
        for (int rr = 0; rr < 2; rr++) {
            int m = mb + i * 16 + rr * 8;
            if (m >= M) continue;
            if (EPI == 0) {
                int b_ = m / NL, l = m - b_ * NL;
#pragma unroll
                for (int j = 0; j < 4; j++) {
#pragma unroll
                    for (int e = 0; e < 2; e++) {
                        int n = nb + j * 8 + e;
                        float v = acc[i][j][rr * 2 + e] + bias[n];
                        int part = n >> 10, c1 = n & 1023;
                        int hh = c1 >> 6, hd = c1 & 63;
                        size_t o = ((((size_t)b_ * NH + hh) * NL + l) << 6) + hd;
                        if (part == 0) {
                            g_QC[o] = v + cbias[c1];
                            g_QP[o] = v + pbias[c1];
                        } else if (part == 1) {
                            g_Kt[o] = v;
                        } else {
                            g_Vt[o] = v;
                        }
                    }
                }
            } else if (EPI == 1) {
                float bm = bias[m];
#pragma unroll
                for (int j = 0; j < 4; j++) {
#pragma unroll
                    for (int e = 0; e < 2; e++) {
                        int n = nb + j * 8 + e;
                        float v = acc[i][j][rr * 2 + e] + bm;
                        int bh = n >> 6, hd = n & 63;
                        g_PT[((((size_t)bh) << 10) + m) * 64 + hd] = v;
                    }
                }
            } else {
#pragma unroll
                for (int j = 0; j < 4; j++) {
                    int n = nb + j * 8;
                    float2 st;
                    st.x = acc[i][j][rr * 2 + 0] + bias[n];
                    st.y = acc[i][j][rr * 2 + 1] + bias[n + 1];
                    *(float2*)(out + (size_t)m * ND + n) = st;
                }
            }
        }
    }
}

// ---------------------------------------------------------------------------
// Tensor-core fused attention. CTA = (i-tile of 64 q, one b,h), 256 thr/8 warps.
// warp w: row group rg=w&3 (16 rows), column half ch=w>>2.
//  score:  S = QC@K^T (tf32) + diag-gather( G = QP@Pband^T (f16) )
//  softmax on fp16 S rows in smem, AV = exp(S)@V (tf32).
// smem 108,160B -> 2 CTAs/SM.
// ---------------------------------------------------------------------------
__global__ void __launch_bounds__(256, 2)
attn_mma(const unsigned char* __restrict__ mask, float* __restrict__ ctx)
{
    extern __shared__ char smraw[];
    __half*   sS  = (__half*)smraw;                   // [64][520] + 64 pad halves
    unsigned* sKG = (unsigned*)(smraw + 66688);       // K/V tf32 frags | G f16 (16,640B)
    unsigned* sP  = (unsigned*)(smraw + 83328);       // P band f16 frags (16,384B)
    unsigned* sQP = (unsigned*)(smraw + 99712);       // QP f16 A-frags (8,192B)
    float*    sSum= (float*)(smraw + 107904);         // [64]
    __half*   sG  = (__half*)sKG;                     // G view: [64][130] halves

    int t = threadIdx.x, lam = t & 31, w = t >> 5;
    int rg = w & 3, ch = w >> 2;
    int it = blockIdx.x, h = blockIdx.y, b = blockIdx.z;
    int i0 = it * 64;
    size_t bh = (size_t)b * NH + h;
    const float* QCg = g_QC + bh * NL * NHD;
    const float* QPg = g_QP + bh * NL * NHD;
    const float* Kg  = g_Kt + bh * NL * NHD;
    const float* Vg  = g_Vt + bh * NL * NHD;
    const float* Pg  = g_PT + bh * NP * NHD;

    // zero sS (incl. pads; AV reads pads multiplied by zeroed V frags)
    for (int idx = t; idx < 16672; idx += 256) ((unsigned*)sS)[idx] = 0u;

    int gr0 = rg * 16 + (lam >> 2);    // local row of this thread's C-frags
    int r0g = i0 + gr0, r1g = r0g + 8;

    // QC A-frags (tf32) in registers: 8 ksteps
    uint4 qcf[8];
#pragma unroll
    for (int ks = 0; ks < 8; ks++) {
        int c0 = ks * 8 + (lam & 3);
        float a0 = (r0g < NL) ? QCg[r0g * 64 + c0]     : 0.f;
        float a1 = (r1g < NL) ? QCg[r1g * 64 + c0]     : 0.f;
        float a2 = (r0g < NL) ? QCg[r0g * 64 + c0 + 4] : 0.f;
        float a3 = (r1g < NL) ? QCg[r1g * 64 + c0 + 4] : 0.f;
        qcf[ks] = make_uint4(cvt_tf32(a0), cvt_tf32(a1), cvt_tf32(a2), cvt_tf32(a3));
    }

    // stage QP f16 A-frags: warp covers (rg_s, 2 of 4 k16-steps)
    {
        int rgs = w & 3;
        int rs0 = i0 + rgs * 16 + (lam >> 2), rs1 = rs0 + 8;
#pragma unroll
        for (int si = 0; si < 2; si++) {
            int s = (w >> 2) * 2 + si;
            int k2 = s * 16 + 2 * (lam & 3);
            float q00 = 0, q01 = 0, q10 = 0, q11 = 0, q02 = 0, q03 = 0, q12 = 0, q13 = 0;
            if (rs0 < NL) {
                q00 = QPg[rs0 * 64 + k2];     q01 = QPg[rs0 * 64 + k2 + 1];
                q02 = QPg[rs0 * 64 + k2 + 8]; q03 = QPg[rs0 * 64 + k2 + 9];
            }
            if (rs1 < NL) {
                q10 = QPg[rs1 * 64 + k2];     q11 = QPg[rs1 * 64 + k2 + 1];
                q12 = QPg[rs1 * 64 + k2 + 8]; q13 = QPg[rs1 * 64 + k2 + 9];
            }
            uint4 v = make_uint4(pkh2(q00, q01), pkh2(q10, q11),
                                 pkh2(q02, q03), pkh2(q12, q13));
            *(uint4*)&sQP[(rgs * 4 + s) * 128 + lam * 4] = v;
        }
    }

    // ===================== score phase =====================
    for (int jt = 0; jt < 9; jt++) {
        int j0 = jt * 64;
        __syncthreads();   // prev gather reads / initial zero+QP staging done
        // stage K_j as tf32 B-frags into sKG  (k-dim = hd, n-dim = key)
#pragma unroll
        for (int u = 0; u < 4; u++) {
            int key = (t >> 4) + u * 16;
            int hd4 = (t & 15) * 4;
            int gk = j0 + key;
            float4 kv = make_float4(0.f, 0.f, 0.f, 0.f);
            if (gk < NL) kv = *(const float4*)(Kg + (size_t)gk * 64 + hd4);
            int ks = hd4 >> 3, khigh = (hd4 & 7) >> 2;
            unsigned base = ks * 520 + (key >> 3) * 64 + (key & 7) * 8 + khigh;
            sKG[base + 0] = cvt_tf32(kv.x);
            sKG[base + 2] = cvt_tf32(kv.y);
            sKG[base + 4] = cvt_tf32(kv.z);
            sKG[base + 6] = cvt_tf32(kv.w);
        }
        // stage P band (128 rows) as f16 B-frags into sP
        int pbase = j0 - i0 + 449;
#pragma unroll
        for (int u = 0; u < 16; u++) {
            int idx = u * 256 + t;
            int c = idx >> 5, d = (idx & 31) * 2;
            int p = pbase + c;
            unsigned hv = 0u;
            if (p >= 0 && p < NP)
                hv = pkh2(Pg[(size_t)p * 64 + d], Pg[(size_t)p * 64 + d + 1]);
            int step = d >> 4, d16 = d & 15;
            sP[step * 1024 + (c >> 3) * 64 + ((c & 7) * 4 + ((d16 & 7) >> 1)) * 2 + (d16 >> 3)] = hv;
        }
        __syncthreads();

        // content MMA (tf32): 4 n8-tiles (this warp's 32 cols)
        float C[4][4];
#pragma unroll
        for (int nt = 0; nt < 4; nt++)
#pragma unroll
            for (int r = 0; r < 4; r++) C[nt][r] = 0.f;
#pragma unroll
        for (int ks = 0; ks < 8; ks++) {
            uint4 av = qcf[ks];
#pragma unroll
            for (int nt = 0; nt < 4; nt++) {
                uint2 bv = *(const uint2*)&sKG[ks * 520 + (ch * 4 + nt) * 64 + lam * 2];
                mma_tf32(C[nt], av, bv);
            }
        }
        // G MMA (f16): 8 n8-tiles (this warp's 64 band cols)
        float G[8][4];
#pragma unroll
        for (int nt = 0; nt < 8; nt++)
#pragma unroll
            for (int r = 0; r < 4; r++) G[nt][r] = 0.f;
#pragma unroll
        for (int s = 0; s < 4; s++) {
            uint4 af = *(const uint4*)&sQP[(rg * 4 + s) * 128 + lam * 4];
#pragma unroll
            for (int nt = 0; nt < 8; nt++) {
                uint2 bv = *(const uint2*)&sP[s * 1024 + (ch * 8 + nt) * 64 + lam * 2];
                mma_f16(G[nt], af, bv);
            }
        }
        __syncthreads();   // all content reads of sKG done before G overwrite
        // store G (f16) into sKG region: [64][130] halves
#pragma unroll
        for (int nt = 0; nt < 8; nt++) {
            int c0 = ch * 64 + nt * 8 + 2 * (lam & 3);
            *(__half2*)&sG[gr0 * 130 + c0]       = __floats2half2_rn(G[nt][0], G[nt][1]);
            *(__half2*)&sG[(gr0 + 8) * 130 + c0] = __floats2half2_rn(G[nt][2], G[nt][3]);
        }
        __syncthreads();   // G visible
        // gather + combine + store S (fp16)
#pragma unroll
        for (int nt = 0; nt < 4; nt++) {
            int jjb = ch * 32 + nt * 8 + 2 * (lam & 3);
            float s0 = C[nt][0] + __half2float(sG[gr0 * 130 + (jjb - gr0 + 63)]);
            float s1 = C[nt][1] + __half2float(sG[gr0 * 130 + (jjb + 1 - gr0 + 63)]);
            float s2 = C[nt][2] + __half2float(sG[(gr0 + 8) * 130 + (jjb - gr0 - 8 + 63)]);
            float s3 = C[nt][3] + __half2float(sG[(gr0 + 8) * 130 + (jjb + 1 - gr0 - 8 + 63)]);
            if (j0 + jjb < NL) {
                *(__half2*)&sS[gr0 * 520 + j0 + jjb]       = __floats2half2_rn(s0, s1);
                *(__half2*)&sS[(gr0 + 8) * 520 + j0 + jjb] = __floats2half2_rn(s2, s3);
            }
        }
    }
    __syncthreads();

    // ===================== softmax (warp per row) =====================
    for (int li = w * 8; li < w * 8 + 8; li++) {
        int i = i0 + li;
        if (i >= NL) { if (lam == 0) sSum[li] = 1.f; continue; }
        const unsigned char* mrow = mask + ((size_t)b * NL + i) * NL;
        __half* srow = &sS[li * 520];
        float mx = -3.4028235e38f;
        for (int j = lam; j < NL; j += 32) {
            float v = __half2float(srow[j]) * 0.125f;
            if (mrow[j]) v = -3.4028235e38f;
            mx = fmaxf(mx, v);
        }
#pragma unroll
        for (int o = 16; o > 0; o >>= 1) mx = fmaxf(mx, __shfl_xor_sync(0xffffffffu, mx, o));
        float s = 0.f;
        for (int j = lam; j < NL; j += 32) {
            float v = __half2float(srow[j]) * 0.125f;
            if (mrow[j]) v = -3.4028235e38f;
            float e = __expf(v - mx);
            srow[j] = __float2half_rn(e);
            s += e;
        }
#pragma unroll
        for (int o = 16; o > 0; o >>= 1) s += __shfl_xor_sync(0xffffffffu, s, o);
        if (lam == 0) sSum[li] = s;
    }
    __syncthreads();

    // ===================== AV phase (tf32) =====================
    float O[4][4];
#pragma unroll
    for (int nt = 0; nt < 4; nt++)
#pragma unroll
        for (int r = 0; r < 4; r++) O[nt][r] = 0.f;

    for (int jt = 0; jt < 9; jt++) {
        int j0 = jt * 64;
        __syncthreads();   // prev MMA reads of sKG done
        // stage V_j as tf32 B-frags: k-dim = key (contraction over j!), n-dim = hd
#pragma unroll
        for (int u = 0; u < 4; u++) {
            int key = (t >> 4) + u * 16;
            int hd4 = (t & 15) * 4;
            int gk = j0 + key;
            float4 kv = make_float4(0.f, 0.f, 0.f, 0.f);
            if (gk < NL) kv = *(const float4*)(Vg + (size_t)gk * 64 + hd4);
            int ks2 = key >> 3, kk = key & 7;
            unsigned base = ks2 * 520 + (hd4 >> 3) * 64 + (hd4 & 7) * 8
                          + (kk & 3) * 2 + (kk >> 2);
            sKG[base + 0]  = cvt_tf32(kv.x);
            sKG[base + 8]  = cvt_tf32(kv.y);
            sKG[base + 16] = cvt_tf32(kv.z);
            sKG[base + 24] = cvt_tf32(kv.w);
        }
        __syncthreads();
#pragma unroll
        for (int ks = 0; ks < 8; ks++) {
            int kc = j0 + ks * 8 + (lam & 3);
            float a0 = __half2float(sS[gr0 * 520 + kc]);
            float a1 = __half2float(sS[(gr0 + 8) * 520 + kc]);
            float a2 = __half2float(sS[gr0 * 520 + kc + 4]);
            float a3 = __half2float(sS[(gr0 + 8) * 520 + kc + 4]);
            uint4 av = make_uint4(cvt_tf32(a0), cvt_tf32(a1), cvt_tf32(a2), cvt_tf32(a3));
#pragma unroll
            for (int nt = 0; nt < 4; nt++) {
                uint2 bv = *(const uint2*)&sKG[ks * 520 + (ch * 4 + nt) * 64 + lam * 2];
                mma_tf32(O[nt], av, bv);
            }
        }
    }

    // epilogue: normalize by row sums, store ctx
    float l0 = 1.f / sSum[gr0];
    float l1 = 1.f / sSum[gr0 + 8];
#pragma unroll
    for (int nt = 0; nt < 4; nt++) {
        int hd = ch * 32 + nt * 8 + 2 * (lam & 3);
        if (r0g < NL) {
            float2 st = make_float2(O[nt][0] * l0, O[nt][1] * l0);
            *(float2*)&ctx[((size_t)b * NL + r0g) * ND + h * 64 + hd] = st;
        }
        if (r1g < NL) {
            float2 st = make_float2(O[nt][2] * l1, O[nt][3] * l1);
            *(float2*)&ctx[((size_t)b * NL + r1g) * ND + h * 64 + hd] = st;
        }
    }
}

// ---------------------------------------------------------------------------
extern "C" void kernel_launch(void* const* d_in, const int* in_sizes, int n_in,
                              void* d_out, int out_size)
{
    const float* x     = (const float*)d_in[0];
    const float* pe    = (const float*)d_in[1];
    const unsigned char* mask = (const unsigned char*)d_in[2];
    const float* qkv_w = (const float*)d_in[3];
    const float* qkv_b = (const float*)d_in[4];
    const float* pos_w = (const float*)d_in[5];
    const float* pos_b = (const float*)d_in[6];
    const float* out_w = (const float*)d_in[7];
    const float* out_b = (const float*)d_in[8];
    const float* cbias = (const float*)d_in[9];
    const float* pbias = (const float*)d_in[10];
    float* out = (float*)d_out;

    float* ctxp = nullptr;
    cudaGetSymbolAddress((void**)&ctxp, g_CTX);

    const int M1 = NB * NL;                 // 8208
    const int ATTN_SMEM = 108160;
    cudaFuncSetAttribute(attn_mma, cudaFuncAttributeMaxDynamicSharedMemorySize, ATTN_SMEM);

    dim3 blk(256);
    gemm_tf32<0><<<dim3(3072 / 128, (M1 + 127) / 128), blk>>>(
        x, qkv_w, M1, 3072, qkv_b, cbias, pbias, nullptr);
    gemm_tf32<1><<<dim3(16384 / 128, 1024 / 128), blk>>>(
        pos_w, pe, 1024, 16384, pos_b, nullptr, nullptr, nullptr);
    attn_mma<<<dim3(9, NH, NB), blk, ATTN_SMEM>>>(mask, ctxp);
    gemm_tf32<2><<<dim3(1024 / 128, (M1 + 127) / 128), blk>>>(
        ctxp, out_w, M1, 1024, out_b, nullptr, nullptr, out);
}